// round 1
// baseline (speedup 1.0000x reference)
#include <cuda_runtime.h>
#include <cuda_bf16.h>
#include <math.h>

#define N_ROWS 8192
#define D_DIM  128

// ---------------- device scratch (no allocations allowed) ----------------
__device__ float  d_F[2][N_ROWS * D_DIM];   // compacted features per class
__device__ float  d_rsq[2][N_ROWS];         // ||x||^2 per compacted row
__device__ int    d_cnt[2];                 // class counts
__device__ float  d_vsum[2][D_DIM];         // per-class sum vector
__device__ double d_acc[4];                 // 0 focal_sum, 1 graph_sum, 2 Snorm0, 3 Snorm1
__device__ double d_cross;                  // sum of relu(1-dist)^2 over cross pairs (unordered once)

__device__ __forceinline__ float warp_sum(float v) {
    #pragma unroll
    for (int o = 16; o > 0; o >>= 1) v += __shfl_xor_sync(0xffffffffu, v, o);
    return v;
}

// ---------------- zero accumulators (runs every launch; graph-replay safe) --
__global__ void zero_kernel() {
    int t = threadIdx.x;
    if (t < 2)  d_cnt[t] = 0;
    if (t < 4)  d_acc[t] = 0.0;
    if (t == 4) d_cross = 0.0;
    if (t < 256) d_vsum[t >> 7][t & 127] = 0.0f;
}

// ---------------- partition + focal + graph + class stats ----------------
// 1024 blocks x 256 threads; one warp per row.
__global__ void __launch_bounds__(256) partition_kernel(
    const float* __restrict__ preds,
    const float* __restrict__ targets,
    const float* __restrict__ features,
    const float* __restrict__ gfeat)
{
    __shared__ float s_v[2][D_DIM];
    __shared__ float s_sn[2];
    __shared__ float s_focal, s_graph;

    int tid = threadIdx.x;
    if (tid < D_DIM) { s_v[0][tid] = 0.0f; s_v[1][tid] = 0.0f; }
    if (tid == 254) { s_sn[0] = 0.0f; s_sn[1] = 0.0f; }
    if (tid == 255) { s_focal = 0.0f; s_graph = 0.0f; }
    __syncthreads();

    int warp = tid >> 5, lane = tid & 31;
    int i = blockIdx.x * 8 + warp;   // always < 8192 with grid=1024

    float4 f = *(const float4*)(features + (size_t)i * D_DIM + lane * 4);
    float nsq = f.x*f.x + f.y*f.y + f.z*f.z + f.w*f.w;
    nsq = warp_sum(nsq);

    float tgt = targets[i];
    int lab = (tgt > 0.5f) ? 1 : 0;

    int idx = 0;
    if (lane == 0) idx = atomicAdd(&d_cnt[lab], 1);
    idx = __shfl_sync(0xffffffffu, idx, 0);

    *(float4*)(d_F[lab] + (size_t)idx * D_DIM + lane * 4) = f;
    if (lane == 0) d_rsq[lab][idx] = nsq;

    atomicAdd(&s_v[lab][lane * 4 + 0], f.x);
    atomicAdd(&s_v[lab][lane * 4 + 1], f.y);
    atomicAdd(&s_v[lab][lane * 4 + 2], f.z);
    atomicAdd(&s_v[lab][lane * 4 + 3], f.w);
    if (lane == 0) atomicAdd(&s_sn[lab], nsq);

    if (lane == 0) {
        // focal loss term for element i
        float p = preds[i];
        float bce = fmaxf(p, 0.0f) - p * tgt + log1pf(expf(-fabsf(p)));
        float pt = expf(-bce);
        float om = 1.0f - pt;
        atomicAdd(&s_focal, 0.25f * om * om * bce);
    }

    if (i >= 1) {
        const float4 a = *(const float4*)(gfeat + (size_t)i       * D_DIM + lane * 4);
        const float4 b = *(const float4*)(gfeat + (size_t)(i - 1) * D_DIM + lane * 4);
        float dx = a.x - b.x, dy = a.y - b.y, dz = a.z - b.z, dw = a.w - b.w;
        float ds = dx*dx + dy*dy + dz*dz + dw*dw;
        ds = warp_sum(ds);
        if (lane == 0) atomicAdd(&s_graph, sqrtf(ds));
    }
    __syncthreads();

    // 256 components -> global vector sums
    {
        float val = s_v[tid >> 7][tid & 127];
        if (val != 0.0f) atomicAdd(&d_vsum[tid >> 7][tid & 127], val);
    }
    if (tid == 0) {
        atomicAdd(&d_acc[0], (double)s_focal);
        atomicAdd(&d_acc[1], (double)s_graph);
        atomicAdd(&d_acc[2], (double)s_sn[0]);
        atomicAdd(&d_acc[3], (double)s_sn[1]);
    }
}

// ---------------- cross-label pairwise relu(1-dist)^2 -------------------
// 128x128 block tile, 8x8 per-thread microtile, BK=32, fp32 FMA.
#define BPITCH 132   // padded m-dim for [k][m] smem tiles (4-way store conflicts only)

__global__ void __launch_bounds__(256, 2) cross_kernel() {
    __shared__ float As[32 * BPITCH];
    __shared__ float Bs[32 * BPITCH];
    __shared__ float red[256];

    int n0 = d_cnt[0], n1 = d_cnt[1];
    int row0 = blockIdx.y * 128, col0 = blockIdx.x * 128;
    if (row0 >= n0 || col0 >= n1) return;

    int tid = threadIdx.x;
    int ty = tid >> 4, tx = tid & 15;

    float acc[8][8];
    #pragma unroll
    for (int i = 0; i < 8; ++i)
        #pragma unroll
        for (int j = 0; j < 8; ++j) acc[i][j] = 0.0f;

    for (int kk = 0; kk < D_DIM; kk += 32) {
        __syncthreads();
        #pragma unroll
        for (int it = 0; it < 4; ++it) {
            int f  = tid + it * 256;
            int r  = f >> 3;
            int c4 = f & 7;
            float4 v = make_float4(0.f, 0.f, 0.f, 0.f);
            if (row0 + r < n0)
                v = *(const float4*)(d_F[0] + (size_t)(row0 + r) * D_DIM + kk + c4 * 4);
            As[(c4 * 4 + 0) * BPITCH + r] = v.x;
            As[(c4 * 4 + 1) * BPITCH + r] = v.y;
            As[(c4 * 4 + 2) * BPITCH + r] = v.z;
            As[(c4 * 4 + 3) * BPITCH + r] = v.w;
            float4 w = make_float4(0.f, 0.f, 0.f, 0.f);
            if (col0 + r < n1)
                w = *(const float4*)(d_F[1] + (size_t)(col0 + r) * D_DIM + kk + c4 * 4);
            Bs[(c4 * 4 + 0) * BPITCH + r] = w.x;
            Bs[(c4 * 4 + 1) * BPITCH + r] = w.y;
            Bs[(c4 * 4 + 2) * BPITCH + r] = w.z;
            Bs[(c4 * 4 + 3) * BPITCH + r] = w.w;
        }
        __syncthreads();

        #pragma unroll 4
        for (int k = 0; k < 32; ++k) {
            float a[8], b[8];
            *(float4*)&a[0] = *(const float4*)(As + k * BPITCH + ty * 8);
            *(float4*)&a[4] = *(const float4*)(As + k * BPITCH + ty * 8 + 4);
            *(float4*)&b[0] = *(const float4*)(Bs + k * BPITCH + tx * 8);
            *(float4*)&b[4] = *(const float4*)(Bs + k * BPITCH + tx * 8 + 4);
            #pragma unroll
            for (int i = 0; i < 8; ++i)
                #pragma unroll
                for (int j = 0; j < 8; ++j)
                    acc[i][j] += a[i] * b[j];
        }
    }

    // epilogue: sq = ra + rb - 2*dot ; add relu(1-sqrt(sq))^2
    int gi0 = row0 + ty * 8, gj0 = col0 + tx * 8;
    float ra[8], rb[8];
    #pragma unroll
    for (int i = 0; i < 8; ++i) ra[i] = (gi0 + i < n0) ? d_rsq[0][gi0 + i] : 0.0f;
    #pragma unroll
    for (int j = 0; j < 8; ++j) rb[j] = (gj0 + j < n1) ? d_rsq[1][gj0 + j] : 0.0f;

    float lsum = 0.0f;
    #pragma unroll
    for (int i = 0; i < 8; ++i) {
        if (gi0 + i >= n0) continue;
        #pragma unroll
        for (int j = 0; j < 8; ++j) {
            if (gj0 + j >= n1) continue;
            float sq = fmaxf(ra[i] + rb[j] - 2.0f * acc[i][j], 0.0f);
            float t = 1.0f - sqrtf(sq);
            if (t > 0.0f) lsum += t * t;
        }
    }

    red[tid] = lsum;
    __syncthreads();
    #pragma unroll
    for (int s = 128; s > 0; s >>= 1) {
        if (tid < s) red[tid] += red[tid + s];
        __syncthreads();
    }
    if (tid == 0 && red[0] != 0.0f) atomicAdd(&d_cross, (double)red[0]);
}

// ---------------- finalize ----------------
__global__ void finalize_kernel(float* out) {
    __shared__ double s[256];
    int t = threadIdx.x;
    double v = (double)d_vsum[t >> 7][t & 127];
    s[t] = v * v;
    __syncthreads();
    for (int st = 64; st > 0; st >>= 1) {
        if ((t & 127) < st) s[t] += s[t + st];
        __syncthreads();
    }
    if (t == 0) {
        double vn0 = s[0], vn1 = s[128];
        double n0 = (double)d_cnt[0], n1 = (double)d_cnt[1];
        // closed form for same-label pairs: sum_sq = 2*(|c|*S_c - ||v_c||^2)
        double same = 2.0 * (n0 * d_acc[2] - vn0) + 2.0 * (n1 * d_acc[3] - vn1);
        double NN = (double)N_ROWS * (double)N_ROWS;
        double contrast = (same + 2.0 * d_cross) / NN;  // cross pairs counted both orders
        double focal = d_acc[0] / (double)N_ROWS;
        double graph = 0.1 * d_acc[1] / (double)(N_ROWS - 1);
        out[0] = (float)(focal + contrast + graph);
    }
}

// ---------------- launch ----------------
extern "C" void kernel_launch(void* const* d_in, const int* in_sizes, int n_in,
                              void* d_out, int out_size) {
    const float* preds    = (const float*)d_in[0];
    const float* targets  = (const float*)d_in[1];
    const float* features = (const float*)d_in[2];
    const float* gfeat    = (const float*)d_in[3];
    float* out = (float*)d_out;

    zero_kernel<<<1, 256>>>();
    partition_kernel<<<N_ROWS / 8, 256>>>(preds, targets, features, gfeat);
    // worst-case tile cover for any n0+n1=8192 split: ceil/128 product <= 33*32
    cross_kernel<<<dim3(33, 33), 256>>>();
    finalize_kernel<<<1, 256>>>(out);
}

// round 2
// speedup vs baseline: 2.1897x; 2.1897x over previous
#include <cuda_runtime.h>
#include <cuda_bf16.h>
#include <math.h>

#define N_ROWS 8192
#define D_DIM  128
#define TK     16          // screening dims (lower-bound projection)
#define SCREEN_THRESH 1.5f
#define CROSS_BLOCKS 1056  // >= max over splits of ceil(n0/128)*ceil(n1/128)

// ---------------- device scratch (zero-initialized at module load; ----------
// ---------------- finalize resets everything for the next replay) -----------
__device__ float  d_F[2][N_ROWS * D_DIM];   // compacted features per class
__device__ float  d_rsq[2][N_ROWS];         // full ||x||^2 per compacted row
__device__ float  d_rsq16[2][N_ROWS];       // first-16-dims partial norm
__device__ int    d_cnt[2];                 // class counts
__device__ float  d_vsum[2][D_DIM];         // per-class sum vector
__device__ double d_acc[4];                 // 0 focal, 1 graph, 2 Snorm0, 3 Snorm1
__device__ double d_cross;                  // sum relu(1-dist)^2 over cross pairs (one order)
__device__ unsigned d_done;                 // completion ticket

__device__ __forceinline__ float warp_sum(float v) {
    #pragma unroll
    for (int o = 16; o > 0; o >>= 1) v += __shfl_xor_sync(0xffffffffu, v, o);
    return v;
}

// ---------------- partition + focal + graph + class stats ----------------
// 1024 blocks x 256 threads; one warp per row, per-block compaction.
__global__ void __launch_bounds__(256) partition_kernel(
    const float* __restrict__ preds,
    const float* __restrict__ targets,
    const float* __restrict__ features,
    const float* __restrict__ gfeat)
{
    __shared__ float s_v[2][D_DIM];
    __shared__ float s_sn[2];
    __shared__ float s_focal, s_graph;
    __shared__ int   s_lab[8];
    __shared__ int   s_base[2];

    int tid = threadIdx.x;
    if (tid < D_DIM) { s_v[0][tid] = 0.0f; s_v[1][tid] = 0.0f; }
    if (tid == 254) { s_sn[0] = 0.0f; s_sn[1] = 0.0f; }
    if (tid == 255) { s_focal = 0.0f; s_graph = 0.0f; }

    int warp = tid >> 5, lane = tid & 31;
    int i = blockIdx.x * 8 + warp;   // < 8192 with grid=1024

    float4 f = *(const float4*)(features + (size_t)i * D_DIM + lane * 4);
    float c  = f.x*f.x + f.y*f.y + f.z*f.z + f.w*f.w;
    float nsq   = warp_sum(c);
    float nsq16 = warp_sum(lane < 4 ? c : 0.0f);   // dims [0,16)

    float tgt = targets[i];
    int lab = (tgt > 0.5f) ? 1 : 0;
    if (lane == 0) s_lab[warp] = lab;
    __syncthreads();

    if (tid == 0) {
        int c1 = 0;
        #pragma unroll
        for (int w = 0; w < 8; ++w) c1 += s_lab[w];
        s_base[0] = atomicAdd(&d_cnt[0], 8 - c1);
        s_base[1] = atomicAdd(&d_cnt[1], c1);
    }
    __syncthreads();

    int rank = 0;
    #pragma unroll
    for (int w = 0; w < 8; ++w) rank += (w < warp && s_lab[w] == lab);
    int idx = s_base[lab] + rank;

    *(float4*)(d_F[lab] + (size_t)idx * D_DIM + lane * 4) = f;
    if (lane == 0) { d_rsq[lab][idx] = nsq; d_rsq16[lab][idx] = nsq16; }

    atomicAdd(&s_v[lab][lane * 4 + 0], f.x);
    atomicAdd(&s_v[lab][lane * 4 + 1], f.y);
    atomicAdd(&s_v[lab][lane * 4 + 2], f.z);
    atomicAdd(&s_v[lab][lane * 4 + 3], f.w);
    if (lane == 0) atomicAdd(&s_sn[lab], nsq);

    if (lane == 0) {
        float p = preds[i];
        float bce = fmaxf(p, 0.0f) - p * tgt + log1pf(expf(-fabsf(p)));
        float pt = expf(-bce);
        float om = 1.0f - pt;
        atomicAdd(&s_focal, 0.25f * om * om * bce);
    }

    if (i >= 1) {
        const float4 a = *(const float4*)(gfeat + (size_t)i       * D_DIM + lane * 4);
        const float4 b = *(const float4*)(gfeat + (size_t)(i - 1) * D_DIM + lane * 4);
        float dx = a.x - b.x, dy = a.y - b.y, dz = a.z - b.z, dw = a.w - b.w;
        float ds = warp_sum(dx*dx + dy*dy + dz*dz + dw*dw);
        if (lane == 0) atomicAdd(&s_graph, sqrtf(ds));
    }
    __syncthreads();

    {
        float val = s_v[tid >> 7][tid & 127];
        if (val != 0.0f) atomicAdd(&d_vsum[tid >> 7][tid & 127], val);
    }
    if (tid == 0) {
        atomicAdd(&d_acc[0], (double)s_focal);
        atomicAdd(&d_acc[1], (double)s_graph);
        atomicAdd(&d_acc[2], (double)s_sn[0]);
        atomicAdd(&d_acc[3], (double)s_sn[1]);
    }
}

// ---------------- cross-label screen (16-dim lower bound) + finalize --------
#define BPITCH 132

__global__ void __launch_bounds__(256, 2) cross_kernel(float* __restrict__ out) {
    __shared__ float As[TK * BPITCH];
    __shared__ float Bs[TK * BPITCH];
    __shared__ float red[256];
    __shared__ unsigned s_ticket;

    int n0 = d_cnt[0], n1 = d_cnt[1];
    int tiles_r = (n0 + 127) >> 7;
    int tiles_c = (n1 + 127) >> 7;
    int tid = threadIdx.x;
    int bid = blockIdx.x;

    if (bid < tiles_r * tiles_c) {
        int tr = bid / tiles_c, tc = bid - tr * tiles_c;
        int row0 = tr * 128, col0 = tc * 128;
        int ty = tid >> 4, tx = tid & 15;

        // load 128x16 tiles of the first-16 dims, transposed [k][m]
        #pragma unroll
        for (int it = 0; it < 2; ++it) {
            int f  = tid + it * 256;     // 0..511
            int r  = f >> 2;             // row 0..127
            int c4 = f & 3;              // float4 within 16 dims
            float4 v = make_float4(0.f, 0.f, 0.f, 0.f);
            if (row0 + r < n0)
                v = *(const float4*)(d_F[0] + (size_t)(row0 + r) * D_DIM + c4 * 4);
            As[(c4 * 4 + 0) * BPITCH + r] = v.x;
            As[(c4 * 4 + 1) * BPITCH + r] = v.y;
            As[(c4 * 4 + 2) * BPITCH + r] = v.z;
            As[(c4 * 4 + 3) * BPITCH + r] = v.w;
            float4 w = make_float4(0.f, 0.f, 0.f, 0.f);
            if (col0 + r < n1)
                w = *(const float4*)(d_F[1] + (size_t)(col0 + r) * D_DIM + c4 * 4);
            Bs[(c4 * 4 + 0) * BPITCH + r] = w.x;
            Bs[(c4 * 4 + 1) * BPITCH + r] = w.y;
            Bs[(c4 * 4 + 2) * BPITCH + r] = w.z;
            Bs[(c4 * 4 + 3) * BPITCH + r] = w.w;
        }
        __syncthreads();

        float acc[8][8];
        #pragma unroll
        for (int i = 0; i < 8; ++i)
            #pragma unroll
            for (int j = 0; j < 8; ++j) acc[i][j] = 0.0f;

        #pragma unroll
        for (int k = 0; k < TK; ++k) {
            float a[8], b[8];
            *(float4*)&a[0] = *(const float4*)(As + k * BPITCH + ty * 8);
            *(float4*)&a[4] = *(const float4*)(As + k * BPITCH + ty * 8 + 4);
            *(float4*)&b[0] = *(const float4*)(Bs + k * BPITCH + tx * 8);
            *(float4*)&b[4] = *(const float4*)(Bs + k * BPITCH + tx * 8 + 4);
            #pragma unroll
            for (int i = 0; i < 8; ++i)
                #pragma unroll
                for (int j = 0; j < 8; ++j)
                    acc[i][j] += a[i] * b[j];
        }

        int gi0 = row0 + ty * 8, gj0 = col0 + tx * 8;
        float ra16[8], rb16[8];
        #pragma unroll
        for (int i = 0; i < 8; ++i) ra16[i] = (gi0 + i < n0) ? d_rsq16[0][gi0 + i] : 0.0f;
        #pragma unroll
        for (int j = 0; j < 8; ++j) rb16[j] = (gj0 + j < n1) ? d_rsq16[1][gj0 + j] : 0.0f;

        float lsum = 0.0f;
        #pragma unroll
        for (int i = 0; i < 8; ++i) {
            if (gi0 + i >= n0) continue;
            #pragma unroll
            for (int j = 0; j < 8; ++j) {
                if (gj0 + j >= n1) continue;
                float sqLB = ra16[i] + rb16[j] - 2.0f * acc[i][j];
                if (sqLB < SCREEN_THRESH) {
                    // exact fp32 recheck (rare path)
                    const float* A = d_F[0] + (size_t)(gi0 + i) * D_DIM;
                    const float* B = d_F[1] + (size_t)(gj0 + j) * D_DIM;
                    float dot = 0.0f;
                    for (int d = 0; d < D_DIM; ++d) dot += A[d] * B[d];
                    float sq = fmaxf(d_rsq[0][gi0 + i] + d_rsq[1][gj0 + j] - 2.0f * dot, 0.0f);
                    float t = 1.0f - sqrtf(sq);
                    if (t > 0.0f) lsum += t * t;
                }
            }
        }

        red[tid] = lsum;
        __syncthreads();
        #pragma unroll
        for (int s = 128; s > 0; s >>= 1) {
            if (tid < s) red[tid] += red[tid + s];
            __syncthreads();
        }
        if (tid == 0 && red[0] != 0.0f) atomicAdd(&d_cross, (double)red[0]);
    }

    // ---- completion ticket: last block finalizes + resets ----
    __threadfence();
    if (tid == 0) s_ticket = atomicAdd(&d_done, 1u);
    __syncthreads();
    if (s_ticket == CROSS_BLOCKS - 1) {
        __threadfence();
        __shared__ double s[256];
        int cls = tid >> 7, comp = tid & 127;
        double v = (double)d_vsum[cls][comp];
        s[tid] = v * v;
        __syncthreads();
        for (int st = 64; st > 0; st >>= 1) {
            if (comp < st) s[tid] += s[tid + st];
            __syncthreads();
        }
        if (tid == 0) {
            double vn0 = s[0], vn1 = s[128];
            double dn0 = (double)n0, dn1 = (double)n1;
            double same = 2.0 * (dn0 * d_acc[2] - vn0) + 2.0 * (dn1 * d_acc[3] - vn1);
            double NN = (double)N_ROWS * (double)N_ROWS;
            double contrast = (same + 2.0 * d_cross) / NN;
            double focal = d_acc[0] / (double)N_ROWS;
            double graph = 0.1 * d_acc[1] / (double)(N_ROWS - 1);
            out[0] = (float)(focal + contrast + graph);
            // reset scalars for next graph replay
            d_cnt[0] = 0; d_cnt[1] = 0;
            d_acc[0] = 0.0; d_acc[1] = 0.0; d_acc[2] = 0.0; d_acc[3] = 0.0;
            d_cross = 0.0;
            d_done = 0u;
        }
        d_vsum[cls][comp] = 0.0f;
    }
}

// ---------------- launch ----------------
extern "C" void kernel_launch(void* const* d_in, const int* in_sizes, int n_in,
                              void* d_out, int out_size) {
    const float* preds    = (const float*)d_in[0];
    const float* targets  = (const float*)d_in[1];
    const float* features = (const float*)d_in[2];
    const float* gfeat    = (const float*)d_in[3];
    float* out = (float*)d_out;

    partition_kernel<<<N_ROWS / 8, 256>>>(preds, targets, features, gfeat);
    cross_kernel<<<CROSS_BLOCKS, 256>>>(out);
}